// round 4
// baseline (speedup 1.0000x reference)
#include <cuda_runtime.h>
#include <cstdint>

// Problem constants (shapes fixed by the dataset)
#define MAX_NODES 50000
#define F_IN   32
#define F_OUT  32
#define NB     4
#define K16    (NB * NB)          // 16 basis products
#define YROW   (K16 * F_OUT)      // 512 floats per node

// Scratch: Y[n, k, o] = sum_i x_j[n,i] * W[k,i,o]   (102.4 MB, device global)
__device__ float g_Y[(size_t)MAX_NODES * YROW];

// ---------------------------------------------------------------------------
// Kernel 0: zero the output (d_out is poisoned before timing)
// ---------------------------------------------------------------------------
__global__ void zero_out_kernel(float4* __restrict__ out, int n4) {
    int i = blockIdx.x * blockDim.x + threadIdx.x;
    if (i < n4) out[i] = make_float4(0.f, 0.f, 0.f, 0.f);
}

// ---------------------------------------------------------------------------
// Kernel 1: Y = X @ W   ([N,32] x [16,32,32] -> [N,16,32])
// 128 threads/block: thread t owns (k = t>>3, og = (t&7)*4) -> 4 consecutive
// outputs of one k-slice. W (64 KB) lives in dynamic smem; each block
// grid-strides over tiles of 8 nodes, x tile staged in smem (broadcast reads).
// ---------------------------------------------------------------------------
#define NPB 8  // nodes per tile

__global__ __launch_bounds__(128, 3) void build_Y_kernel(
    const float* __restrict__ x,       // [N, 32]
    const float* __restrict__ w,       // [16, 32, 32]
    int n_nodes)
{
    extern __shared__ float smem[];
    float* Wsh = smem;                          // 16*32*32 floats = 64 KB
    float (*xs)[F_IN] = (float (*)[F_IN])(smem + K16 * F_IN * F_OUT);

    // Stage W
    for (int idx = threadIdx.x; idx < K16 * F_IN * F_OUT; idx += blockDim.x)
        Wsh[idx] = w[idx];
    __syncthreads();

    const int k  = threadIdx.x >> 3;
    const int og = (threadIdx.x & 7) * 4;
    const float* Wk = &Wsh[k * (F_IN * F_OUT) + og];

    for (int n0 = blockIdx.x * NPB; n0 < n_nodes; n0 += gridDim.x * NPB) {
        __syncthreads();  // protect xs from previous tile
        // Stage x tile: NPB*32 = 256 floats, coalesced
        for (int idx = threadIdx.x; idx < NPB * F_IN; idx += blockDim.x) {
            int n = idx >> 5, i = idx & 31;
            int gn = n0 + n;
            xs[n][i] = (gn < n_nodes) ? x[gn * F_IN + i] : 0.f;
        }
        __syncthreads();

        float4 acc[NPB];
        #pragma unroll
        for (int n = 0; n < NPB; n++) acc[n] = make_float4(0.f, 0.f, 0.f, 0.f);

        #pragma unroll
        for (int i = 0; i < F_IN; i++) {
            float4 wv = *(const float4*)&Wk[i * F_OUT];   // conflict-free LDS.128
            #pragma unroll
            for (int n = 0; n < NPB; n++) {
                float xv = xs[n][i];                      // smem broadcast
                acc[n].x = fmaf(xv, wv.x, acc[n].x);
                acc[n].y = fmaf(xv, wv.y, acc[n].y);
                acc[n].z = fmaf(xv, wv.z, acc[n].z);
                acc[n].w = fmaf(xv, wv.w, acc[n].w);
            }
        }

        #pragma unroll
        for (int n = 0; n < NPB; n++) {
            int gn = n0 + n;
            if (gn < n_nodes)
                *(float4*)&g_Y[(size_t)gn * YROW + k * F_OUT + og] = acc[n];
        }
    }
}

// ---------------------------------------------------------------------------
// Kernel 2: per-edge bilinear gather from Y + fp32 atomic scatter to out.
// One warp per edge, lane = output channel o.
// Hat basis on [-1,1] with 4 centers: only 2 adjacent centers are nonzero per
// dim -> 4 (kx,ky) corners with bilinear coefficients.
// ---------------------------------------------------------------------------
__global__ __launch_bounds__(256) void edge_msg_kernel(
    const int*   __restrict__ ei,   // [2, E] : row0 = dst, row1 = src
    const float* __restrict__ ea,   // [E, 2]
    float*       __restrict__ out,  // [N, 32]
    int E)
{
    const int lane = threadIdx.x & 31;
    const int e = (blockIdx.x * blockDim.x + threadIdx.x) >> 5;
    if (e >= E) return;

    const int dst = ei[e];
    const int src = ei[E + e];
    const float ax = ea[2 * e];
    const float ay = ea[2 * e + 1];

    // u = (x+1)/dx in [0,3]; cell j = floor(u) clamped to [0,2]; t = u - j
    float ux = fminf(fmaxf((ax + 1.0f) * 1.5f, 0.0f), 3.0f);
    float uy = fminf(fmaxf((ay + 1.0f) * 1.5f, 0.0f), 3.0f);
    int jx = min((int)ux, 2);
    int jy = min((int)uy, 2);
    float tx = ux - (float)jx;
    float ty = uy - (float)jy;
    float sx = 1.0f - tx, sy = 1.0f - ty;

    // k = kx*4 + ky ; corner (jx,jy): +32 per ky step, +128 per kx step
    const float* Yp = &g_Y[(size_t)src * YROW + (jx * NB + jy) * F_OUT + lane];
    float m = sx * (sy * Yp[0]   + ty * Yp[32])
            + tx * (sy * Yp[128] + ty * Yp[160]);

    atomicAdd(out + dst * F_OUT + lane, m);
}

// ---------------------------------------------------------------------------
// Launch
// Inputs (metadata order): x_i, x_j, edge_index, edge_attr, weight
// ---------------------------------------------------------------------------
extern "C" void kernel_launch(void* const* d_in, const int* in_sizes, int n_in,
                              void* d_out, int out_size)
{
    const float* x_j = (const float*)d_in[1];
    const int*   ei  = (const int*)  d_in[2];
    const float* ea  = (const float*)d_in[3];
    const float* w   = (const float*)d_in[4];
    float* out = (float*)d_out;

    const int n_nodes = in_sizes[0] / F_IN;
    const int E       = in_sizes[2] / 2;

    // K0: zero output
    {
        int n4 = out_size / 4;
        zero_out_kernel<<<(n4 + 255) / 256, 256>>>((float4*)d_out, n4);
    }

    // K1: build Y  (dynamic smem: 64 KB W + x tile)
    {
        static const int smem_bytes = (K16 * F_IN * F_OUT + NPB * F_IN) * (int)sizeof(float);
        cudaFuncSetAttribute(build_Y_kernel,
                             cudaFuncAttributeMaxDynamicSharedMemorySize, smem_bytes);
        build_Y_kernel<<<444, 128, smem_bytes>>>(x_j, w, n_nodes);
    }

    // K2: edge gather + scatter (one warp per edge)
    {
        int warps_per_block = 256 / 32;
        int blocks = (E + warps_per_block - 1) / warps_per_block;
        edge_msg_kernel<<<blocks, 256>>>(ei, ea, out, E);
    }

    (void)n_in; (void)out;
}

// round 5
// speedup vs baseline: 1.0025x; 1.0025x over previous
#include <cuda_runtime.h>
#include <cstdint>

// Problem constants (shapes fixed by the dataset)
#define MAX_NODES 50000
#define F_IN   32
#define F_OUT  32
#define NB     4
#define K16    (NB * NB)          // 16 basis products
#define YROW   (K16 * F_OUT)      // 512 floats per node

// Scratch: Y[n, k, o] = sum_i x_j[n,i] * W[k,i,o]   (102.4 MB, device global)
__device__ float g_Y[(size_t)MAX_NODES * YROW];

// ---------------------------------------------------------------------------
// Kernel 0: zero the output (d_out is poisoned before timing)
// ---------------------------------------------------------------------------
__global__ void zero_out_kernel(float4* __restrict__ out, int n4) {
    int i = blockIdx.x * blockDim.x + threadIdx.x;
    if (i < n4) out[i] = make_float4(0.f, 0.f, 0.f, 0.f);
}

// ---------------------------------------------------------------------------
// Kernel 1: Y = X @ W   ([N,32] x [16,32,32] -> [N,16,32])
// 128 threads/block: thread t owns (k = t>>3, og = (t&7)*4) -> 4 consecutive
// outputs of one k-slice. W (64 KB) lives in dynamic smem; each block
// grid-strides over tiles of 8 nodes, x tile staged in smem (broadcast reads).
// ---------------------------------------------------------------------------
#define NPB 8  // nodes per tile

__global__ __launch_bounds__(128, 3) void build_Y_kernel(
    const float* __restrict__ x,       // [N, 32]
    const float* __restrict__ w,       // [16, 32, 32]
    int n_nodes)
{
    extern __shared__ float smem[];
    float* Wsh = smem;                          // 16*32*32 floats = 64 KB
    float (*xs)[F_IN] = (float (*)[F_IN])(smem + K16 * F_IN * F_OUT);

    // Stage W
    for (int idx = threadIdx.x; idx < K16 * F_IN * F_OUT; idx += blockDim.x)
        Wsh[idx] = w[idx];
    __syncthreads();

    const int k  = threadIdx.x >> 3;
    const int og = (threadIdx.x & 7) * 4;
    const float* Wk = &Wsh[k * (F_IN * F_OUT) + og];

    for (int n0 = blockIdx.x * NPB; n0 < n_nodes; n0 += gridDim.x * NPB) {
        __syncthreads();  // protect xs from previous tile
        // Stage x tile: NPB*32 = 256 floats, coalesced
        for (int idx = threadIdx.x; idx < NPB * F_IN; idx += blockDim.x) {
            int n = idx >> 5, i = idx & 31;
            int gn = n0 + n;
            xs[n][i] = (gn < n_nodes) ? x[gn * F_IN + i] : 0.f;
        }
        __syncthreads();

        float4 acc[NPB];
        #pragma unroll
        for (int n = 0; n < NPB; n++) acc[n] = make_float4(0.f, 0.f, 0.f, 0.f);

        #pragma unroll
        for (int i = 0; i < F_IN; i++) {
            float4 wv = *(const float4*)&Wk[i * F_OUT];   // conflict-free LDS.128
            #pragma unroll
            for (int n = 0; n < NPB; n++) {
                float xv = xs[n][i];                      // smem broadcast
                acc[n].x = fmaf(xv, wv.x, acc[n].x);
                acc[n].y = fmaf(xv, wv.y, acc[n].y);
                acc[n].z = fmaf(xv, wv.z, acc[n].z);
                acc[n].w = fmaf(xv, wv.w, acc[n].w);
            }
        }

        #pragma unroll
        for (int n = 0; n < NPB; n++) {
            int gn = n0 + n;
            if (gn < n_nodes)
                *(float4*)&g_Y[(size_t)gn * YROW + k * F_OUT + og] = acc[n];
        }
    }
}

// ---------------------------------------------------------------------------
// Kernel 2: per-edge bilinear gather from Y + fp32 atomic scatter to out.
// One warp per edge, lane = output channel o.
// Hat basis on [-1,1] with 4 centers: only 2 adjacent centers are nonzero per
// dim -> 4 (kx,ky) corners with bilinear coefficients.
// ---------------------------------------------------------------------------
__global__ __launch_bounds__(256) void edge_msg_kernel(
    const int*   __restrict__ ei,   // [2, E] : row0 = dst, row1 = src
    const float* __restrict__ ea,   // [E, 2]
    float*       __restrict__ out,  // [N, 32]
    int E)
{
    const int lane = threadIdx.x & 31;
    const int e = (blockIdx.x * blockDim.x + threadIdx.x) >> 5;
    if (e >= E) return;

    const int dst = ei[e];
    const int src = ei[E + e];
    const float ax = ea[2 * e];
    const float ay = ea[2 * e + 1];

    // u = (x+1)/dx in [0,3]; cell j = floor(u) clamped to [0,2]; t = u - j
    float ux = fminf(fmaxf((ax + 1.0f) * 1.5f, 0.0f), 3.0f);
    float uy = fminf(fmaxf((ay + 1.0f) * 1.5f, 0.0f), 3.0f);
    int jx = min((int)ux, 2);
    int jy = min((int)uy, 2);
    float tx = ux - (float)jx;
    float ty = uy - (float)jy;
    float sx = 1.0f - tx, sy = 1.0f - ty;

    // k = kx*4 + ky ; corner (jx,jy): +32 per ky step, +128 per kx step
    const float* Yp = &g_Y[(size_t)src * YROW + (jx * NB + jy) * F_OUT + lane];
    float m = sx * (sy * Yp[0]   + ty * Yp[32])
            + tx * (sy * Yp[128] + ty * Yp[160]);

    atomicAdd(out + dst * F_OUT + lane, m);
}

// ---------------------------------------------------------------------------
// Launch
// Inputs (metadata order): x_i, x_j, edge_index, edge_attr, weight
// ---------------------------------------------------------------------------
extern "C" void kernel_launch(void* const* d_in, const int* in_sizes, int n_in,
                              void* d_out, int out_size)
{
    const float* x_j = (const float*)d_in[1];
    const int*   ei  = (const int*)  d_in[2];
    const float* ea  = (const float*)d_in[3];
    const float* w   = (const float*)d_in[4];
    float* out = (float*)d_out;

    const int n_nodes = in_sizes[0] / F_IN;
    const int E       = in_sizes[2] / 2;

    // K0: zero output
    {
        int n4 = out_size / 4;
        zero_out_kernel<<<(n4 + 255) / 256, 256>>>((float4*)d_out, n4);
    }

    // K1: build Y  (dynamic smem: 64 KB W + x tile)
    {
        static const int smem_bytes = (K16 * F_IN * F_OUT + NPB * F_IN) * (int)sizeof(float);
        cudaFuncSetAttribute(build_Y_kernel,
                             cudaFuncAttributeMaxDynamicSharedMemorySize, smem_bytes);
        build_Y_kernel<<<444, 128, smem_bytes>>>(x_j, w, n_nodes);
    }

    // K2: edge gather + scatter (one warp per edge)
    {
        int warps_per_block = 256 / 32;
        int blocks = (E + warps_per_block - 1) / warps_per_block;
        edge_msg_kernel<<<blocks, 256>>>(ei, ea, out, E);
    }

    (void)n_in; (void)out;
}

// round 6
// speedup vs baseline: 1.8821x; 1.8773x over previous
#include <cuda_runtime.h>
#include <cuda_fp16.h>
#include <cstdint>

// Problem constants (shapes fixed by the dataset)
#define MAX_NODES 50000
#define F_IN   32
#define F_OUT  32
#define NB     4
#define K16    (NB * NB)          // 16 basis products
#define YROW   (K16 * F_OUT)      // 512 values per node

// Scratch: Y[n, k, o] = sum_i x_j[n,i] * W[k,i,o]  in fp16 (51.2 MB -> L2-resident)
__device__ __half g_Y[(size_t)MAX_NODES * YROW];

struct alignas(8) Half4 { __half2 a, b; };

// ---------------------------------------------------------------------------
// Kernel 1: zero out, then Y = X @ W   ([N,32] x [16,32,32] -> [N,16,32] fp16)
// 128 threads/block: thread t owns (k = t>>3, og = (t&7)*4). W (64 KB) in smem;
// grid-stride over tiles of 8 nodes, x tile staged in smem (broadcast reads).
// ---------------------------------------------------------------------------
#define NPB 8  // nodes per tile

__global__ __launch_bounds__(128, 3) void build_Y_kernel(
    const float* __restrict__ x,       // [N, 32]
    const float* __restrict__ w,       // [16, 32, 32]
    float4*      __restrict__ out4,    // [N*32/4] -- zeroed here (poisoned by harness)
    int n_nodes)
{
    extern __shared__ float smem[];
    float* Wsh = smem;                          // 16*32*32 floats = 64 KB
    float (*xs)[F_IN] = (float (*)[F_IN])(smem + K16 * F_IN * F_OUT);

    // Zero the output (K2 runs after this kernel completes; same stream)
    {
        int n4 = n_nodes * (F_OUT / 4);
        for (int i = blockIdx.x * blockDim.x + threadIdx.x; i < n4;
             i += gridDim.x * blockDim.x)
            out4[i] = make_float4(0.f, 0.f, 0.f, 0.f);
    }

    // Stage W
    for (int idx = threadIdx.x; idx < K16 * F_IN * F_OUT; idx += blockDim.x)
        Wsh[idx] = w[idx];
    __syncthreads();

    const int k  = threadIdx.x >> 3;
    const int og = (threadIdx.x & 7) * 4;
    const float* Wk = &Wsh[k * (F_IN * F_OUT) + og];

    for (int n0 = blockIdx.x * NPB; n0 < n_nodes; n0 += gridDim.x * NPB) {
        __syncthreads();  // protect xs from previous tile
        for (int idx = threadIdx.x; idx < NPB * F_IN; idx += blockDim.x) {
            int n = idx >> 5, i = idx & 31;
            int gn = n0 + n;
            xs[n][i] = (gn < n_nodes) ? x[gn * F_IN + i] : 0.f;
        }
        __syncthreads();

        float4 acc[NPB];
        #pragma unroll
        for (int n = 0; n < NPB; n++) acc[n] = make_float4(0.f, 0.f, 0.f, 0.f);

        #pragma unroll
        for (int i = 0; i < F_IN; i++) {
            float4 wv = *(const float4*)&Wk[i * F_OUT];   // conflict-free LDS.128
            #pragma unroll
            for (int n = 0; n < NPB; n++) {
                float xv = xs[n][i];                      // smem broadcast
                acc[n].x = fmaf(xv, wv.x, acc[n].x);
                acc[n].y = fmaf(xv, wv.y, acc[n].y);
                acc[n].z = fmaf(xv, wv.z, acc[n].z);
                acc[n].w = fmaf(xv, wv.w, acc[n].w);
            }
        }

        #pragma unroll
        for (int n = 0; n < NPB; n++) {
            int gn = n0 + n;
            if (gn < n_nodes) {
                Half4 h;
                h.a = __floats2half2_rn(acc[n].x, acc[n].y);
                h.b = __floats2half2_rn(acc[n].z, acc[n].w);
                *(Half4*)&g_Y[(size_t)gn * YROW + k * F_OUT + og] = h;
            }
        }
    }
}

// ---------------------------------------------------------------------------
// Kernel 2: bilinear gather from fp16 Y + vectorized fp32 reduction scatter.
// 8 threads per edge; thread owns 4 consecutive outputs -> one
// red.global.add.v4.f32 per thread (4x fewer RED instrs than scalar).
// Hat basis on [-1,1] with 4 centers: exactly 2 adjacent nonzero terms per
// dim -> 4 (kx,ky) corners with bilinear coefficients.
// ---------------------------------------------------------------------------
__global__ __launch_bounds__(256) void edge_msg_kernel(
    const int*    __restrict__ ei,   // [2, E] : row0 = dst, row1 = src
    const float2* __restrict__ ea,   // [E] (pairs)
    float*        __restrict__ out,  // [N, 32]
    int E)
{
    const int t = blockIdx.x * blockDim.x + threadIdx.x;
    const int e = t >> 3;            // 8 threads per edge
    const int c = (t & 7) << 2;      // base of this thread's 4 outputs
    if (e >= E) return;

    const int dst = __ldg(&ei[e]);
    const int src = __ldg(&ei[E + e]);
    const float2 a = __ldg(&ea[e]);

    // u = (x+1)/dx in [0,3]; cell j = floor(u) clamped to [0,2]; t = u - j
    float ux = fminf(fmaxf((a.x + 1.0f) * 1.5f, 0.0f), 3.0f);
    float uy = fminf(fmaxf((a.y + 1.0f) * 1.5f, 0.0f), 3.0f);
    int jx = min((int)ux, 2);
    int jy = min((int)uy, 2);
    float tx = ux - (float)jx;
    float ty = uy - (float)jy;
    float sx = 1.0f - tx, sy = 1.0f - ty;

    const float c00 = sx * sy, c01 = sx * ty, c10 = tx * sy, c11 = tx * ty;

    // k = kx*4 + ky ; corner (jx,jy): +32 elems per ky step, +128 per kx step
    const __half* Yp = &g_Y[(size_t)src * YROW + (jx * NB + jy) * F_OUT + c];
    Half4 v00 = *(const Half4*)(Yp);
    Half4 v01 = *(const Half4*)(Yp + 32);
    Half4 v10 = *(const Half4*)(Yp + 128);
    Half4 v11 = *(const Half4*)(Yp + 160);

    float2 f00a = __half22float2(v00.a), f00b = __half22float2(v00.b);
    float2 f01a = __half22float2(v01.a), f01b = __half22float2(v01.b);
    float2 f10a = __half22float2(v10.a), f10b = __half22float2(v10.b);
    float2 f11a = __half22float2(v11.a), f11b = __half22float2(v11.b);

    float r0 = c00 * f00a.x + c01 * f01a.x + c10 * f10a.x + c11 * f11a.x;
    float r1 = c00 * f00a.y + c01 * f01a.y + c10 * f10a.y + c11 * f11a.y;
    float r2 = c00 * f00b.x + c01 * f01b.x + c10 * f10b.x + c11 * f11b.x;
    float r3 = c00 * f00b.y + c01 * f01b.y + c10 * f10b.y + c11 * f11b.y;

    float* dp = out + dst * F_OUT + c;   // 16B-aligned (c multiple of 4)
    asm volatile("red.global.add.v4.f32 [%0], {%1, %2, %3, %4};"
                 :: "l"(dp), "f"(r0), "f"(r1), "f"(r2), "f"(r3)
                 : "memory");
}

// ---------------------------------------------------------------------------
// Launch
// Inputs (metadata order): x_i, x_j, edge_index, edge_attr, weight
// ---------------------------------------------------------------------------
extern "C" void kernel_launch(void* const* d_in, const int* in_sizes, int n_in,
                              void* d_out, int out_size)
{
    const float*  x_j = (const float*) d_in[1];
    const int*    ei  = (const int*)   d_in[2];
    const float2* ea  = (const float2*)d_in[3];
    const float*  w   = (const float*) d_in[4];
    float* out = (float*)d_out;

    const int n_nodes = in_sizes[0] / F_IN;
    const int E       = in_sizes[2] / 2;

    // K1: zero out + build Y  (dynamic smem: 64 KB W + x tile)
    {
        static const int smem_bytes =
            (K16 * F_IN * F_OUT + NPB * F_IN) * (int)sizeof(float);
        cudaFuncSetAttribute(build_Y_kernel,
                             cudaFuncAttributeMaxDynamicSharedMemorySize, smem_bytes);
        build_Y_kernel<<<444, 128, smem_bytes>>>(x_j, w, (float4*)d_out, n_nodes);
    }

    // K2: edge gather + vectorized reduction scatter (8 threads per edge)
    {
        long long threads = (long long)E * 8;
        int blocks = (int)((threads + 255) / 256);
        edge_msg_kernel<<<blocks, 256>>>(ei, ea, out, E);
    }

    (void)n_in; (void)out_size;
}

// round 7
// speedup vs baseline: 2.2474x; 1.1941x over previous
#include <cuda_runtime.h>
#include <cuda_fp16.h>
#include <cstdint>

// Problem constants (shapes fixed by the dataset)
#define MAX_NODES 50000
#define F_IN   32
#define F_OUT  32
#define NB     4
#define K16    (NB * NB)          // 16 basis products
#define YROW   (K16 * F_OUT)      // 512 values per node (j = k*32 + o)

// Scratch: Y[n, j] = sum_i x_j[n,i] * W[j>>5, i, j&31]  in fp16 (51.2 MB)
__device__ __half g_Y[(size_t)MAX_NODES * YROW];

struct alignas(16) Half8 { __half2 h[4]; };

// ---------------------------------------------------------------------------
// Kernel 1: zero out, then Y = X @ Wbig via HMMA m16n8k16 (fp16 in, fp32 acc).
//   Wbig[i, j] = w[j>>5][i][j&31]  ->  one GEMM [N,32] x [32,512].
// 256 threads = 8 warps; each warp owns a 16-node m-tile and sweeps all 64
// n-tiles (8 cols each), 2 k-chunks of 16. WbigT[j][i] staged in smem fp16
// (rows padded to 40 halves -> conflict-free ldmatrix). A-fragments loaded
// directly from global fp32 as float2 pairs (exact m16n8k16 A layout).
// ---------------------------------------------------------------------------
#define WPAD 40   // halves per Ws row (80 B stride: ldmatrix conflict-free)

__global__ __launch_bounds__(256, 3) void build_Y_mma(
    const float* __restrict__ x,     // [N, 32] fp32
    const float* __restrict__ w,     // [16, 32, 32] fp32
    float4*      __restrict__ out4,  // [N*32/4] -- zeroed here
    int n_nodes)
{
    __shared__ __half Ws[512 * WPAD];   // 40 KB

    // Zero the output (poisoned by harness); K2 runs after this kernel.
    {
        int n4 = n_nodes * (F_OUT / 4);
        for (int i = blockIdx.x * blockDim.x + threadIdx.x; i < n4;
             i += gridDim.x * blockDim.x)
            out4[i] = make_float4(0.f, 0.f, 0.f, 0.f);
    }

    // Stage WbigT[j][i] = w[k][i][o],  j = k*32 + o  (coalesced global reads)
    for (int idx = threadIdx.x; idx < K16 * F_IN * F_OUT; idx += blockDim.x) {
        int k = idx >> 10, i = (idx >> 5) & 31, o = idx & 31;
        Ws[(k * 32 + o) * WPAD + i] = __float2half_rn(w[idx]);
    }
    __syncthreads();

    const int lane = threadIdx.x & 31;
    const int warp = threadIdx.x >> 5;

    // ldmatrix.x2 source addresses for B (lanes 0-7: mat0, 8-15: mat1)
    const unsigned bbase = (unsigned)__cvta_generic_to_shared(Ws);
    const int brow  = lane & 7;          // row within n-tile
    const int bhalf = (lane >> 3) & 1;   // mat1 -> k columns +8

    const int mtiles = n_nodes >> 4;     // N divisible by 16 (50000)

    for (int mt = blockIdx.x * 8 + warp; mt < mtiles; mt += gridDim.x * 8) {
        const int n0 = mt << 4;

        // A fragments: 2 k-chunks x 4 pairs, straight from global fp32.
        // pair p: row = n0 + l/4 + 8*(p&1), col = kc*16 + (l%4)*2 + 8*(p>>1)
        uint32_t afr[2][4];
        const int ar = n0 + (lane >> 2);
        const int ac = (lane & 3) * 2;
        #pragma unroll
        for (int kc = 0; kc < 2; kc++)
            #pragma unroll
            for (int p = 0; p < 4; p++) {
                int r = ar + ((p & 1) << 3);
                int cc = kc * 16 + ac + ((p >> 1) << 3);
                float2 v = *(const float2*)&x[r * F_IN + cc];
                __half2 h = __floats2half2_rn(v.x, v.y);
                afr[kc][p] = *(uint32_t*)&h;
            }

        const size_t yb = (size_t)(ar)*YROW;          // row l/4
        const size_t yb8 = (size_t)(ar + 8) * YROW;   // row l/4 + 8

        #pragma unroll 4
        for (int nt = 0; nt < 64; nt++) {
            unsigned s0 = bbase +
                (((nt * 8 + brow) * WPAD) + bhalf * 8) * 2u;
            uint32_t b00, b01, b10, b11;
            asm volatile("ldmatrix.sync.aligned.m8n8.x2.shared.b16 {%0,%1}, [%2];"
                         : "=r"(b00), "=r"(b01) : "r"(s0));
            asm volatile("ldmatrix.sync.aligned.m8n8.x2.shared.b16 {%0,%1}, [%2];"
                         : "=r"(b10), "=r"(b11) : "r"(s0 + 32u));

            float d0 = 0.f, d1 = 0.f, d2 = 0.f, d3 = 0.f;
            asm volatile(
                "mma.sync.aligned.m16n8k16.row.col.f32.f16.f16.f32 "
                "{%0,%1,%2,%3}, {%4,%5,%6,%7}, {%8,%9}, {%0,%1,%2,%3};"
                : "+f"(d0), "+f"(d1), "+f"(d2), "+f"(d3)
                : "r"(afr[0][0]), "r"(afr[0][1]), "r"(afr[0][2]), "r"(afr[0][3]),
                  "r"(b00), "r"(b01));
            asm volatile(
                "mma.sync.aligned.m16n8k16.row.col.f32.f16.f16.f32 "
                "{%0,%1,%2,%3}, {%4,%5,%6,%7}, {%8,%9}, {%0,%1,%2,%3};"
                : "+f"(d0), "+f"(d1), "+f"(d2), "+f"(d3)
                : "r"(afr[1][0]), "r"(afr[1][1]), "r"(afr[1][2]), "r"(afr[1][3]),
                  "r"(b10), "r"(b11));

            // D: lane l -> C[l/4][nt*8+(l%4)*2 +{0,1}] and row+8
            int col = nt * 8 + ac;
            *(__half2*)&g_Y[yb  + col] = __floats2half2_rn(d0, d1);
            *(__half2*)&g_Y[yb8 + col] = __floats2half2_rn(d2, d3);
        }
    }
}

// ---------------------------------------------------------------------------
// Kernel 2: bilinear gather from fp16 Y + vectorized fp32 reduction scatter.
// 4 threads per edge; thread owns 8 consecutive outputs: each corner is one
// LDG.128 (16 B of the 64 B corner row) -> half the warp-instruction count of
// the 8-thread version; two red.global.add.v4.f32 per thread.
// ---------------------------------------------------------------------------
__global__ __launch_bounds__(256) void edge_msg_kernel(
    const int*    __restrict__ ei,   // [2, E] : row0 = dst, row1 = src
    const float2* __restrict__ ea,   // [E]
    float*        __restrict__ out,  // [N, 32]
    int E)
{
    const int t = blockIdx.x * blockDim.x + threadIdx.x;
    const int e = t >> 2;            // 4 threads per edge
    const int c = (t & 3) << 3;      // base of this thread's 8 outputs
    if (e >= E) return;

    const int dst = __ldg(&ei[e]);
    const int src = __ldg(&ei[E + e]);
    const float2 a = __ldg(&ea[e]);

    // u = (x+1)/dx in [0,3]; cell j = floor(u) clamped to [0,2]; t = u - j
    float ux = fminf(fmaxf((a.x + 1.0f) * 1.5f, 0.0f), 3.0f);
    float uy = fminf(fmaxf((a.y + 1.0f) * 1.5f, 0.0f), 3.0f);
    int jx = min((int)ux, 2);
    int jy = min((int)uy, 2);
    float tx = ux - (float)jx;
    float ty = uy - (float)jy;
    float sx = 1.0f - tx, sy = 1.0f - ty;

    const float c00 = sx * sy, c01 = sx * ty, c10 = tx * sy, c11 = tx * ty;

    // k = kx*4 + ky ; corner (jx,jy): +32 elems per ky step, +128 per kx step
    const __half* Yp = &g_Y[(size_t)src * YROW + (jx * NB + jy) * F_OUT + c];
    Half8 v00 = *(const Half8*)(Yp);
    Half8 v01 = *(const Half8*)(Yp + 32);
    Half8 v10 = *(const Half8*)(Yp + 128);
    Half8 v11 = *(const Half8*)(Yp + 160);

    float r[8];
    #pragma unroll
    for (int q = 0; q < 4; q++) {
        float2 f00 = __half22float2(v00.h[q]);
        float2 f01 = __half22float2(v01.h[q]);
        float2 f10 = __half22float2(v10.h[q]);
        float2 f11 = __half22float2(v11.h[q]);
        r[2*q]   = c00 * f00.x + c01 * f01.x + c10 * f10.x + c11 * f11.x;
        r[2*q+1] = c00 * f00.y + c01 * f01.y + c10 * f10.y + c11 * f11.y;
    }

    float* dp = out + dst * F_OUT + c;   // 32B-aligned (c multiple of 8)
    asm volatile("red.global.add.v4.f32 [%0], {%1, %2, %3, %4};"
                 :: "l"(dp), "f"(r[0]), "f"(r[1]), "f"(r[2]), "f"(r[3])
                 : "memory");
    asm volatile("red.global.add.v4.f32 [%0], {%1, %2, %3, %4};"
                 :: "l"(dp + 4), "f"(r[4]), "f"(r[5]), "f"(r[6]), "f"(r[7])
                 : "memory");
}

// ---------------------------------------------------------------------------
// Launch
// Inputs (metadata order): x_i, x_j, edge_index, edge_attr, weight
// ---------------------------------------------------------------------------
extern "C" void kernel_launch(void* const* d_in, const int* in_sizes, int n_in,
                              void* d_out, int out_size)
{
    const float*  x_j = (const float*) d_in[1];
    const int*    ei  = (const int*)   d_in[2];
    const float2* ea  = (const float2*)d_in[3];
    const float*  w   = (const float*) d_in[4];
    float* out = (float*)d_out;

    const int n_nodes = in_sizes[0] / F_IN;
    const int E       = in_sizes[2] / 2;

    // K1: zero out + build Y via tensor cores
    {
        int mtiles = n_nodes >> 4;                 // 3125
        int blocks = (mtiles + 7) / 8;             // 391
        build_Y_mma<<<blocks, 256>>>(x_j, w, (float4*)d_out, n_nodes);
    }

    // K2: edge gather + vectorized reduction scatter (4 threads per edge)
    {
        long long threads = (long long)E * 4;
        int blocks = (int)((threads + 255) / 256);
        edge_msg_kernel<<<blocks, 256>>>(ei, ea, out, E);
    }

    (void)n_in; (void)out_size;
}

// round 8
// speedup vs baseline: 3.0591x; 1.3611x over previous
#include <cuda_runtime.h>
#include <cuda_fp16.h>
#include <cstdint>

// Problem constants (shapes fixed by the dataset)
#define MAX_NODES 50000
#define F_IN   32
#define F_OUT  32
#define NB     4
#define K16    (NB * NB)          // 16 basis products
#define YROW   (K16 * F_OUT)      // 512 values per node (j = k*32 + o)

// Scratch: Y[n, j] = sum_i x_j[n,i] * W[j>>5, i, j&31]  in fp16 (51.2 MB)
__device__ __half g_Y[(size_t)MAX_NODES * YROW];

struct alignas(8)  Half4 { __half2 a, b; };

// ---------------------------------------------------------------------------
// Kernel 1: zero out, then Y = X @ Wbig via HMMA m16n8k16 (fp16 in, fp32 acc).
//   Wbig[i, j] = w[j>>5][i][j&31]  ->  one GEMM [N,32] x [32,512].
// 256 threads = 8 warps; each warp owns a 16-node m-tile, sweeps 64 n-tiles
// in 2 phases of 32. D fragments are staged in a per-warp smem tile and
// flushed with coalesced 512B row stores (4 wf/instr instead of 8 wf per
// scattered STG.32 -> 8x fewer store wavefronts).
// ---------------------------------------------------------------------------
#define WPAD  40    // halves per Ws row (80 B stride: ldmatrix conflict-free)
#define DCOLS 264   // 256 data halves + 8 pad (row stride 528 B, STS conflict-free)

__global__ __launch_bounds__(256, 2) void build_Y_mma(
    const float* __restrict__ x,     // [N, 32] fp32
    const float* __restrict__ w,     // [16, 32, 32] fp32
    float4*      __restrict__ out4,  // [N*32/4] -- zeroed here
    int n_nodes)
{
    extern __shared__ __half smem[];
    __half* Ws = smem;                                 // 512*WPAD = 40 KB
    __half* Dw = smem + 512 * WPAD +
                 (threadIdx.x >> 5) * (16 * DCOLS);    // per-warp 16x264 tile

    // Zero the output (poisoned by harness); K2 runs after this kernel.
    {
        int n4 = n_nodes * (F_OUT / 4);
        for (int i = blockIdx.x * blockDim.x + threadIdx.x; i < n4;
             i += gridDim.x * blockDim.x)
            out4[i] = make_float4(0.f, 0.f, 0.f, 0.f);
    }

    // Stage WbigT[j][i] = w[k][i][o],  j = k*32 + o  (coalesced global reads)
    for (int idx = threadIdx.x; idx < K16 * F_IN * F_OUT; idx += blockDim.x) {
        int k = idx >> 10, i = (idx >> 5) & 31, o = idx & 31;
        Ws[(k * 32 + o) * WPAD + i] = __float2half_rn(w[idx]);
    }
    __syncthreads();

    const int lane = threadIdx.x & 31;

    // ldmatrix.x2 source addresses for B (lanes 0-7: mat0, 8-15: mat1)
    const unsigned bbase = (unsigned)__cvta_generic_to_shared(Ws);
    const int brow  = lane & 7;          // row within n-tile
    const int bhalf = (lane >> 3) & 1;   // mat1 -> k columns +8

    const int mtiles = n_nodes >> 4;     // N divisible by 16 (50000)
    const int warp_gl = blockIdx.x * 8 + (threadIdx.x >> 5);

    for (int mt = warp_gl; mt < mtiles; mt += gridDim.x * 8) {
        const int n0 = mt << 4;

        // A fragments: 2 k-chunks x 4 pairs, straight from global fp32.
        // pair p: row = n0 + l/4 + 8*(p&1), col = kc*16 + (l%4)*2 + 8*(p>>1)
        uint32_t afr[2][4];
        const int ar = n0 + (lane >> 2);
        const int ac = (lane & 3) * 2;
        #pragma unroll
        for (int kc = 0; kc < 2; kc++)
            #pragma unroll
            for (int p = 0; p < 4; p++) {
                int r = ar + ((p & 1) << 3);
                int cc = kc * 16 + ac + ((p >> 1) << 3);
                float2 v = *(const float2*)&x[r * F_IN + cc];
                __half2 h = __floats2half2_rn(v.x, v.y);
                afr[kc][p] = *(uint32_t*)&h;
            }

        __half* d_lo = &Dw[(lane >> 2) * DCOLS + ac];       // row l/4
        __half* d_hi = &Dw[((lane >> 2) + 8) * DCOLS + ac]; // row l/4 + 8

        #pragma unroll
        for (int ph = 0; ph < 2; ph++) {
            #pragma unroll 4
            for (int ntl = 0; ntl < 32; ntl++) {
                const int nt = ph * 32 + ntl;
                unsigned s0 = bbase +
                    (((nt * 8 + brow) * WPAD) + bhalf * 8) * 2u;
                uint32_t b00, b01, b10, b11;
                asm volatile("ldmatrix.sync.aligned.m8n8.x2.shared.b16 {%0,%1}, [%2];"
                             : "=r"(b00), "=r"(b01) : "r"(s0));
                asm volatile("ldmatrix.sync.aligned.m8n8.x2.shared.b16 {%0,%1}, [%2];"
                             : "=r"(b10), "=r"(b11) : "r"(s0 + 32u));

                float d0 = 0.f, d1 = 0.f, d2 = 0.f, d3 = 0.f;
                asm volatile(
                    "mma.sync.aligned.m16n8k16.row.col.f32.f16.f16.f32 "
                    "{%0,%1,%2,%3}, {%4,%5,%6,%7}, {%8,%9}, {%0,%1,%2,%3};"
                    : "+f"(d0), "+f"(d1), "+f"(d2), "+f"(d3)
                    : "r"(afr[0][0]), "r"(afr[0][1]), "r"(afr[0][2]), "r"(afr[0][3]),
                      "r"(b00), "r"(b01));
                asm volatile(
                    "mma.sync.aligned.m16n8k16.row.col.f32.f16.f16.f32 "
                    "{%0,%1,%2,%3}, {%4,%5,%6,%7}, {%8,%9}, {%0,%1,%2,%3};"
                    : "+f"(d0), "+f"(d1), "+f"(d2), "+f"(d3)
                    : "r"(afr[1][0]), "r"(afr[1][1]), "r"(afr[1][2]), "r"(afr[1][3]),
                      "r"(b10), "r"(b11));

                // Stage D in smem (conflict-free STS.32)
                *(__half2*)&d_lo[ntl * 8] = __floats2half2_rn(d0, d1);
                *(__half2*)&d_hi[ntl * 8] = __floats2half2_rn(d2, d3);
            }
            __syncwarp();

            // Coalesced flush: 16 rows x 512 B; one row per STG.128 instr
            // (32 lanes x 16 B contiguous = 4 wavefronts).
            #pragma unroll
            for (int it = 0; it < 16; it++) {
                int i = it * 32 + lane;
                int r = i >> 5, c = i & 31;
                *(int4*)&g_Y[(size_t)(n0 + r) * YROW + ph * 256 + c * 8] =
                    *(const int4*)&Dw[r * DCOLS + c * 8];
            }
            __syncwarp();
        }
    }
}

// ---------------------------------------------------------------------------
// Kernel 2: bilinear gather from fp16 Y + vectorized fp32 reduction scatter.
// 8 threads per edge; thread owns 4 consecutive outputs -> one
// red.global.add.v4.f32 per thread. (Measured-best operating point: LDG.64
// corner loads keep lines-per-instruction low, avoiding within-LDG replays.)
// ---------------------------------------------------------------------------
__global__ __launch_bounds__(256) void edge_msg_kernel(
    const int*    __restrict__ ei,   // [2, E] : row0 = dst, row1 = src
    const float2* __restrict__ ea,   // [E]
    float*        __restrict__ out,  // [N, 32]
    int E)
{
    const int t = blockIdx.x * blockDim.x + threadIdx.x;
    const int e = t >> 3;            // 8 threads per edge
    const int c = (t & 7) << 2;      // base of this thread's 4 outputs
    if (e >= E) return;

    const int dst = __ldg(&ei[e]);
    const int src = __ldg(&ei[E + e]);
    const float2 a = __ldg(&ea[e]);

    // u = (x+1)/dx in [0,3]; cell j = floor(u) clamped to [0,2]; t = u - j
    float ux = fminf(fmaxf((a.x + 1.0f) * 1.5f, 0.0f), 3.0f);
    float uy = fminf(fmaxf((a.y + 1.0f) * 1.5f, 0.0f), 3.0f);
    int jx = min((int)ux, 2);
    int jy = min((int)uy, 2);
    float tx = ux - (float)jx;
    float ty = uy - (float)jy;
    float sx = 1.0f - tx, sy = 1.0f - ty;

    const float c00 = sx * sy, c01 = sx * ty, c10 = tx * sy, c11 = tx * ty;

    // k = kx*4 + ky ; corner (jx,jy): +32 elems per ky step, +128 per kx step
    const __half* Yp = &g_Y[(size_t)src * YROW + (jx * NB + jy) * F_OUT + c];
    Half4 v00 = *(const Half4*)(Yp);
    Half4 v01 = *(const Half4*)(Yp + 32);
    Half4 v10 = *(const Half4*)(Yp + 128);
    Half4 v11 = *(const Half4*)(Yp + 160);

    float2 f00a = __half22float2(v00.a), f00b = __half22float2(v00.b);
    float2 f01a = __half22float2(v01.a), f01b = __half22float2(v01.b);
    float2 f10a = __half22float2(v10.a), f10b = __half22float2(v10.b);
    float2 f11a = __half22float2(v11.a), f11b = __half22float2(v11.b);

    float r0 = c00 * f00a.x + c01 * f01a.x + c10 * f10a.x + c11 * f11a.x;
    float r1 = c00 * f00a.y + c01 * f01a.y + c10 * f10a.y + c11 * f11a.y;
    float r2 = c00 * f00b.x + c01 * f01b.x + c10 * f10b.x + c11 * f11b.x;
    float r3 = c00 * f00b.y + c01 * f01b.y + c10 * f10b.y + c11 * f11b.y;

    float* dp = out + dst * F_OUT + c;   // 16B-aligned (c multiple of 4)
    asm volatile("red.global.add.v4.f32 [%0], {%1, %2, %3, %4};"
                 :: "l"(dp), "f"(r0), "f"(r1), "f"(r2), "f"(r3)
                 : "memory");
}

// ---------------------------------------------------------------------------
// Launch
// Inputs (metadata order): x_i, x_j, edge_index, edge_attr, weight
// ---------------------------------------------------------------------------
extern "C" void kernel_launch(void* const* d_in, const int* in_sizes, int n_in,
                              void* d_out, int out_size)
{
    const float*  x_j = (const float*) d_in[1];
    const int*    ei  = (const int*)   d_in[2];
    const float2* ea  = (const float2*)d_in[3];
    const float*  w   = (const float*) d_in[4];
    float* out = (float*)d_out;

    const int n_nodes = in_sizes[0] / F_IN;
    const int E       = in_sizes[2] / 2;

    // K1: zero out + build Y via tensor cores, smem-staged coalesced stores
    {
        static const int smem_bytes =
            (512 * WPAD + 8 * 16 * DCOLS) * (int)sizeof(__half);  // ~106 KB
        cudaFuncSetAttribute(build_Y_mma,
                             cudaFuncAttributeMaxDynamicSharedMemorySize, smem_bytes);
        int mtiles = n_nodes >> 4;                 // 3125
        int blocks = (mtiles + 7) / 8;
        if (blocks > 296) blocks = 296;            // 2 blocks/SM, grid-stride
        build_Y_mma<<<blocks, 256, smem_bytes>>>(x_j, w, (float4*)d_out, n_nodes);
    }

    // K2: edge gather + vectorized reduction scatter (8 threads per edge)
    {
        long long threads = (long long)E * 8;
        int blocks = (int)((threads + 255) / 256);
        edge_msg_kernel<<<blocks, 256>>>(ei, ea, out, E);
    }

    (void)n_in; (void)out_size;
}